// round 1
// baseline (speedup 1.0000x reference)
#include <cuda_runtime.h>
#include <math.h>

#define BSZ 8
#define SEQ 8192
#define DM  128
#define HH  128
#define NC  64      // chunks per sequence
#define CS  128     // chunk size (tokens)

// ---------------- scratch (device globals; no allocation allowed) -----------
__device__ float g_at[BSZ * SEQ * HH];        // 33.5 MB
__device__ float g_bt[BSZ * SEQ * HH];        // 33.5 MB
__device__ float g_stA[2][BSZ][NC][HH];       // per-chunk product of a
__device__ float g_stB[2][BSZ][NC][HH];       // per-chunk zero-init scan result
__device__ float g_hin[2][BSZ][NC][HH];       // incoming state per chunk
__device__ float g_scalars[BSZ][6];           // s1,b1,g1,s2,b2,g2 per batch

__device__ __forceinline__ float sigmoidf_(float v) {
    return 1.f / (1.f + expf(-v));
}
__device__ __forceinline__ float geluf_(float v) {
    float u = v + 0.044715f * v * v * v;
    return 0.5f * v * (1.f + tanhf(0.7978845608028654f * u));
}

// ---------------- K0: per-batch conditioning scalars ------------------------
__global__ void k0_scalars(const float* __restrict__ c,
    const float* w0, const float* b0, const float* w1, const float* b1,
    const float* w2, const float* b2, const float* w3, const float* b3,
    const float* w4, const float* b4, const float* w5, const float* b5)
{
    __shared__ float red[128];
    int b = blockIdx.x, tid = threadIdx.x;
    float cv = c[b * 128 + tid];
    const float* ws[6] = {w0, w1, w2, w3, w4, w5};
    const float* bs[6] = {b0, b1, b2, b3, b4, b5};
    for (int j = 0; j < 6; j++) {
        red[tid] = cv * ws[j][tid];
        __syncthreads();
        for (int off = 64; off > 0; off >>= 1) {
            if (tid < off) red[tid] += red[tid + off];
            __syncthreads();
        }
        if (tid == 0) g_scalars[b][j] = red[0] + bs[j][0];
        __syncthreads();
    }
}

// ---------------- K1: LN -> LN -> (u, gates) -> a_t, b_t --------------------
// 64-token tile per block, 256 threads. 3 register-tiled fp32 GEMMs.
__global__ __launch_bounds__(256) void k1_pre(
    const float* __restrict__ x,   const float* __restrict__ Win,
    const float* __restrict__ bin, const float* __restrict__ pos,
    const float* __restrict__ Wi,  const float* __restrict__ bi,
    const float* __restrict__ Wr,  const float* __restrict__ br,
    const float* __restrict__ avec)
{
    __shared__ float A[64][128];   // ln2h tile, later overwritten with u
    __shared__ float LA[128];
    int tid = threadIdx.x;
    int to  = blockIdx.x * 64;     // global token base
    int b   = to >> 13;
    int tib = to & (SEQ - 1);      // token-in-batch base
    if (tid < 128) LA[tid] = logf(avec[tid]);
    float s1  = g_scalars[b][0];
    float b1s = g_scalars[b][1];
    float alpha = 1.f + s1;

    // ---- stage 1: two layernorms (token handled by 4 threads, 32 ch each)
    {
        int tt = tid >> 2, q = tid & 3;
        const float4* xp = reinterpret_cast<const float4*>(x + (to + tt) * 128 + q * 32);
        float4 v[8];
#pragma unroll
        for (int i = 0; i < 8; i++) v[i] = xp[i];
        float s = 0.f, ss = 0.f;
#pragma unroll
        for (int i = 0; i < 8; i++) {
            s  += v[i].x + v[i].y + v[i].z + v[i].w;
            ss += v[i].x * v[i].x + v[i].y * v[i].y + v[i].z * v[i].z + v[i].w * v[i].w;
        }
        s  += __shfl_xor_sync(0xffffffffu, s, 1);
        s  += __shfl_xor_sync(0xffffffffu, s, 2);
        ss += __shfl_xor_sync(0xffffffffu, ss, 1);
        ss += __shfl_xor_sync(0xffffffffu, ss, 2);
        float m   = s * (1.f / 128.f);
        float var = ss * (1.f / 128.f) - m * m;
        float rs  = rsqrtf(var + 1e-6f);
        float s2 = 0.f, ss2 = 0.f;
#pragma unroll
        for (int i = 0; i < 8; i++) {
            v[i].x = fmaf(alpha, (v[i].x - m) * rs, b1s);
            v[i].y = fmaf(alpha, (v[i].y - m) * rs, b1s);
            v[i].z = fmaf(alpha, (v[i].z - m) * rs, b1s);
            v[i].w = fmaf(alpha, (v[i].w - m) * rs, b1s);
            s2  += v[i].x + v[i].y + v[i].z + v[i].w;
            ss2 += v[i].x * v[i].x + v[i].y * v[i].y + v[i].z * v[i].z + v[i].w * v[i].w;
        }
        s2  += __shfl_xor_sync(0xffffffffu, s2, 1);
        s2  += __shfl_xor_sync(0xffffffffu, s2, 2);
        ss2 += __shfl_xor_sync(0xffffffffu, ss2, 1);
        ss2 += __shfl_xor_sync(0xffffffffu, ss2, 2);
        float m2   = s2 * (1.f / 128.f);
        float var2 = ss2 * (1.f / 128.f) - m2 * m2;
        float rs2  = rsqrtf(var2 + 1e-6f);
        float4* Ap = reinterpret_cast<float4*>(&A[tt][q * 32]);
#pragma unroll
        for (int i = 0; i < 8; i++) {
            float4 o;
            o.x = (v[i].x - m2) * rs2; o.y = (v[i].y - m2) * rs2;
            o.z = (v[i].z - m2) * rs2; o.w = (v[i].w - m2) * rs2;
            Ap[i] = o;
        }
    }
    __syncthreads();

    // ---- stage 2: u = ln2h @ Win  (tile 8 tok x 4 ch per thread)
    int tr = tid >> 5, tc = tid & 31;
    float acc[8][4];
#pragma unroll
    for (int i = 0; i < 8; i++)
#pragma unroll
        for (int j = 0; j < 4; j++) acc[i][j] = 0.f;
    {
        const float4* W4 = reinterpret_cast<const float4*>(Win);
        for (int k = 0; k < 128; k++) {
            float4 w = W4[k * 32 + tc];
#pragma unroll
            for (int i = 0; i < 8; i++) {
                float av = A[tr * 8 + i][k];
                acc[i][0] = fmaf(av, w.x, acc[i][0]);
                acc[i][1] = fmaf(av, w.y, acc[i][1]);
                acc[i][2] = fmaf(av, w.z, acc[i][2]);
                acc[i][3] = fmaf(av, w.w, acc[i][3]);
            }
        }
    }
    __syncthreads();
    // write u (acc + bias + pos_emb) back into A
    {
        float4 bv = reinterpret_cast<const float4*>(bin)[tc];
#pragma unroll
        for (int i = 0; i < 8; i++) {
            int t = tr * 8 + i;
            float4 pv = reinterpret_cast<const float4*>(pos + (tib + t) * 128)[tc];
            float4 o;
            o.x = acc[i][0] + bv.x + pv.x;
            o.y = acc[i][1] + bv.y + pv.y;
            o.z = acc[i][2] + bv.z + pv.z;
            o.w = acc[i][3] + bv.w + pv.w;
            *reinterpret_cast<float4*>(&A[t][tc * 4]) = o;
        }
    }
    __syncthreads();

    // ---- stage 3: gates (two GEMMs sharing a-fragment)
    float ai[8][4], ar[8][4];
#pragma unroll
    for (int i = 0; i < 8; i++)
#pragma unroll
        for (int j = 0; j < 4; j++) { ai[i][j] = 0.f; ar[i][j] = 0.f; }
    {
        const float4* Wi4 = reinterpret_cast<const float4*>(Wi);
        const float4* Wr4 = reinterpret_cast<const float4*>(Wr);
        for (int k = 0; k < 128; k++) {
            float4 wi = Wi4[k * 32 + tc];
            float4 wr = Wr4[k * 32 + tc];
#pragma unroll
            for (int i = 0; i < 8; i++) {
                float av = A[tr * 8 + i][k];
                ai[i][0] = fmaf(av, wi.x, ai[i][0]);
                ai[i][1] = fmaf(av, wi.y, ai[i][1]);
                ai[i][2] = fmaf(av, wi.z, ai[i][2]);
                ai[i][3] = fmaf(av, wi.w, ai[i][3]);
                ar[i][0] = fmaf(av, wr.x, ar[i][0]);
                ar[i][1] = fmaf(av, wr.y, ar[i][1]);
                ar[i][2] = fmaf(av, wr.z, ar[i][2]);
                ar[i][3] = fmaf(av, wr.w, ar[i][3]);
            }
        }
    }
    float4 biv = reinterpret_cast<const float4*>(bi)[tc];
    float4 brv = reinterpret_cast<const float4*>(br)[tc];
    float la0 = LA[tc * 4 + 0], la1 = LA[tc * 4 + 1];
    float la2 = LA[tc * 4 + 2], la3 = LA[tc * 4 + 3];
#pragma unroll
    for (int i = 0; i < 8; i++) {
        int t = tr * 8 + i;
        float4 uv = *reinterpret_cast<const float4*>(&A[t][tc * 4]);
        int idx = (to + t) * 128 + tc * 4;
        float4 av4, bv4;
        {
            float gi = sigmoidf_(ai[i][0] + biv.x);
            float gr = sigmoidf_(ar[i][0] + brv.x);
            float atv = expf(8.f * gr * la0);
            av4.x = atv;
            bv4.x = sqrtf(fmaxf(1.f - atv * atv, 0.f)) * gi * uv.x;
        }
        {
            float gi = sigmoidf_(ai[i][1] + biv.y);
            float gr = sigmoidf_(ar[i][1] + brv.y);
            float atv = expf(8.f * gr * la1);
            av4.y = atv;
            bv4.y = sqrtf(fmaxf(1.f - atv * atv, 0.f)) * gi * uv.y;
        }
        {
            float gi = sigmoidf_(ai[i][2] + biv.z);
            float gr = sigmoidf_(ar[i][2] + brv.z);
            float atv = expf(8.f * gr * la2);
            av4.z = atv;
            bv4.z = sqrtf(fmaxf(1.f - atv * atv, 0.f)) * gi * uv.z;
        }
        {
            float gi = sigmoidf_(ai[i][3] + biv.w);
            float gr = sigmoidf_(ar[i][3] + brv.w);
            float atv = expf(8.f * gr * la3);
            av4.w = atv;
            bv4.w = sqrtf(fmaxf(1.f - atv * atv, 0.f)) * gi * uv.w;
        }
        *reinterpret_cast<float4*>(g_at + idx) = av4;
        *reinterpret_cast<float4*>(g_bt + idx) = bv4;
    }
}

// ---------------- K2a: per-chunk scan states (both directions) --------------
__global__ __launch_bounds__(256) void k2a_chunk()
{
    int blk = blockIdx.x;
    int b = blk >> 6, ci = blk & 63;
    int tid = threadIdx.x;
    int dir = tid >> 7, h = tid & 127;
    int base = ((b << 13) + (ci << 7)) * 128 + h;
    float Ap = 1.f, Bv = 0.f;
    if (dir == 0) {
#pragma unroll 4
        for (int s = 0; s < CS; s++) {
            int idx = base + (s << 7);
            float a = g_at[idx], bb = g_bt[idx];
            Ap *= a;
            Bv = fmaf(a, Bv, bb);
        }
    } else {
#pragma unroll 4
        for (int s = CS - 1; s >= 0; s--) {
            int idx = base + (s << 7);
            float a = g_at[idx], bb = g_bt[idx];
            Ap *= a;
            Bv = fmaf(a, Bv, bb);
        }
    }
    g_stA[dir][b][ci][h] = Ap;
    g_stB[dir][b][ci][h] = Bv;
}

// ---------------- K2b: chunk-level prefix scan ------------------------------
__global__ void k2b_prefix()
{
    int b = blockIdx.x & 7, dir = blockIdx.x >> 3;
    int h = threadIdx.x;
    float hin = 0.f;
    if (dir == 0) {
        for (int ci = 0; ci < NC; ci++) {
            g_hin[0][b][ci][h] = hin;
            hin = fmaf(g_stA[0][b][ci][h], hin, g_stB[0][b][ci][h]);
        }
    } else {
        for (int ci = NC - 1; ci >= 0; ci--) {
            g_hin[1][b][ci][h] = hin;
            hin = fmaf(g_stA[1][b][ci][h], hin, g_stB[1][b][ci][h]);
        }
    }
}

// ---------------- K3: re-scan chunk into smem + out-GEMM + gated residual ---
// 128-token chunk; hf/hb live only in shared memory (64 KB each).
__global__ __launch_bounds__(256) void k3_scan_out(
    const float* __restrict__ x, const float* __restrict__ Wout,
    const float* __restrict__ bout, float* __restrict__ out)
{
    extern __shared__ float sm3[];
    float* HF = sm3;                // [128][128]
    float* HB = sm3 + 128 * 128;    // [128][128]
    int blk = blockIdx.x;
    int b = blk >> 6, ci = blk & 63;
    int tid = threadIdx.x;
    {
        int dir = tid >> 7, h = tid & 127;
        int base = ((b << 13) + (ci << 7)) * 128 + h;
        float hc = g_hin[dir][b][ci][h];
        if (dir == 0) {
#pragma unroll 4
            for (int s = 0; s < CS; s++) {
                int idx = base + (s << 7);
                hc = fmaf(g_at[idx], hc, g_bt[idx]);
                HF[(s << 7) + h] = hc;
            }
        } else {
#pragma unroll 4
            for (int s = CS - 1; s >= 0; s--) {
                int idx = base + (s << 7);
                hc = fmaf(g_at[idx], hc, g_bt[idx]);
                HB[(s << 7) + h] = hc;
            }
        }
    }
    __syncthreads();

    // GEMM: r[128 tok][128 d] = HF @ Wout[0:128] + HB @ Wout[128:256]
    int r = tid >> 4, c = tid & 15;        // 8 tok x 8 ch per thread
    float acc[8][8];
#pragma unroll
    for (int i = 0; i < 8; i++)
#pragma unroll
        for (int j = 0; j < 8; j++) acc[i][j] = 0.f;
    const float4* W4 = reinterpret_cast<const float4*>(Wout);
    for (int k = 0; k < 128; k++) {
        float4 w0 = W4[k * 32 + c * 2];
        float4 w1 = W4[k * 32 + c * 2 + 1];
#pragma unroll
        for (int i = 0; i < 8; i++) {
            float av = HF[((r * 8 + i) << 7) + k];
            acc[i][0] = fmaf(av, w0.x, acc[i][0]);
            acc[i][1] = fmaf(av, w0.y, acc[i][1]);
            acc[i][2] = fmaf(av, w0.z, acc[i][2]);
            acc[i][3] = fmaf(av, w0.w, acc[i][3]);
            acc[i][4] = fmaf(av, w1.x, acc[i][4]);
            acc[i][5] = fmaf(av, w1.y, acc[i][5]);
            acc[i][6] = fmaf(av, w1.z, acc[i][6]);
            acc[i][7] = fmaf(av, w1.w, acc[i][7]);
        }
    }
    for (int k = 0; k < 128; k++) {
        float4 w0 = W4[(128 + k) * 32 + c * 2];
        float4 w1 = W4[(128 + k) * 32 + c * 2 + 1];
#pragma unroll
        for (int i = 0; i < 8; i++) {
            float av = HB[((r * 8 + i) << 7) + k];
            acc[i][0] = fmaf(av, w0.x, acc[i][0]);
            acc[i][1] = fmaf(av, w0.y, acc[i][1]);
            acc[i][2] = fmaf(av, w0.z, acc[i][2]);
            acc[i][3] = fmaf(av, w0.w, acc[i][3]);
            acc[i][4] = fmaf(av, w1.x, acc[i][4]);
            acc[i][5] = fmaf(av, w1.y, acc[i][5]);
            acc[i][6] = fmaf(av, w1.z, acc[i][6]);
            acc[i][7] = fmaf(av, w1.w, acc[i][7]);
        }
    }
    float g1 = g_scalars[b][2];
    float4 bo0 = reinterpret_cast<const float4*>(bout)[c * 2];
    float4 bo1 = reinterpret_cast<const float4*>(bout)[c * 2 + 1];
#pragma unroll
    for (int i = 0; i < 8; i++) {
        int t = (b << 13) + (ci << 7) + r * 8 + i;
        const float4* xp = reinterpret_cast<const float4*>(x + t * 128 + c * 8);
        float4 x0 = xp[0], x1 = xp[1];
        float4 o0, o1;
        o0.x = fmaf(g1, acc[i][0] + bo0.x, x0.x);
        o0.y = fmaf(g1, acc[i][1] + bo0.y, x0.y);
        o0.z = fmaf(g1, acc[i][2] + bo0.z, x0.z);
        o0.w = fmaf(g1, acc[i][3] + bo0.w, x0.w);
        o1.x = fmaf(g1, acc[i][4] + bo1.x, x1.x);
        o1.y = fmaf(g1, acc[i][5] + bo1.y, x1.y);
        o1.z = fmaf(g1, acc[i][6] + bo1.z, x1.z);
        o1.w = fmaf(g1, acc[i][7] + bo1.w, x1.w);
        float4* op = reinterpret_cast<float4*>(out + t * 128 + c * 8);
        op[0] = o0;
        op[1] = o1;
    }
}

// ---------------- K4: conditioned LN -> GELU MLP -> gated residual ----------
// 64-token tile, 512 threads, in-place on d_out.
__global__ __launch_bounds__(512) void k4_mlp(
    float* __restrict__ out, const float* __restrict__ W1,
    const float* __restrict__ b1v, const float* __restrict__ W2,
    const float* __restrict__ b2v)
{
    extern __shared__ float sm4[];
    float* HS = sm4;                 // [64][128]
    float* M1 = sm4 + 64 * 128;      // [64][512]
    int tid = threadIdx.x;
    int to = blockIdx.x * 64;
    int b = to >> 13;
    float s2 = g_scalars[b][3], b2s = g_scalars[b][4], g2 = g_scalars[b][5];
    float alpha = 1.f + s2;

    // LN: token handled by 8 threads, 16 ch each
    {
        int tt = tid >> 3, oc = tid & 7;
        const float4* xp = reinterpret_cast<const float4*>(out + (to + tt) * 128 + oc * 16);
        float4 v[4];
#pragma unroll
        for (int i = 0; i < 4; i++) v[i] = xp[i];
        float s = 0.f, ss = 0.f;
#pragma unroll
        for (int i = 0; i < 4; i++) {
            s  += v[i].x + v[i].y + v[i].z + v[i].w;
            ss += v[i].x * v[i].x + v[i].y * v[i].y + v[i].z * v[i].z + v[i].w * v[i].w;
        }
        s  += __shfl_xor_sync(0xffffffffu, s, 1);
        s  += __shfl_xor_sync(0xffffffffu, s, 2);
        s  += __shfl_xor_sync(0xffffffffu, s, 4);
        ss += __shfl_xor_sync(0xffffffffu, ss, 1);
        ss += __shfl_xor_sync(0xffffffffu, ss, 2);
        ss += __shfl_xor_sync(0xffffffffu, ss, 4);
        float m   = s * (1.f / 128.f);
        float var = ss * (1.f / 128.f) - m * m;
        float rs  = rsqrtf(var + 1e-6f);
        float4* hp = reinterpret_cast<float4*>(&HS[tt * 128 + oc * 16]);
#pragma unroll
        for (int i = 0; i < 4; i++) {
            float4 o;
            o.x = fmaf(alpha, (v[i].x - m) * rs, b2s);
            o.y = fmaf(alpha, (v[i].y - m) * rs, b2s);
            o.z = fmaf(alpha, (v[i].z - m) * rs, b2s);
            o.w = fmaf(alpha, (v[i].w - m) * rs, b2s);
            hp[i] = o;
        }
    }
    __syncthreads();

    // GEMM1: 64x512, k=128; tile 4 tok x 16 ch per thread
    int r = tid >> 5, c = tid & 31;
    float acc[4][16];
#pragma unroll
    for (int i = 0; i < 4; i++)
#pragma unroll
        for (int j = 0; j < 16; j++) acc[i][j] = 0.f;
    {
        const float4* W14 = reinterpret_cast<const float4*>(W1); // [k][128 f4]
        for (int k = 0; k < 128; k++) {
            float4 w0 = W14[k * 128 + c * 4 + 0];
            float4 w1 = W14[k * 128 + c * 4 + 1];
            float4 w2 = W14[k * 128 + c * 4 + 2];
            float4 w3 = W14[k * 128 + c * 4 + 3];
#pragma unroll
            for (int i = 0; i < 4; i++) {
                float av = HS[(r * 4 + i) * 128 + k];
                acc[i][0]  = fmaf(av, w0.x, acc[i][0]);
                acc[i][1]  = fmaf(av, w0.y, acc[i][1]);
                acc[i][2]  = fmaf(av, w0.z, acc[i][2]);
                acc[i][3]  = fmaf(av, w0.w, acc[i][3]);
                acc[i][4]  = fmaf(av, w1.x, acc[i][4]);
                acc[i][5]  = fmaf(av, w1.y, acc[i][5]);
                acc[i][6]  = fmaf(av, w1.z, acc[i][6]);
                acc[i][7]  = fmaf(av, w1.w, acc[i][7]);
                acc[i][8]  = fmaf(av, w2.x, acc[i][8]);
                acc[i][9]  = fmaf(av, w2.y, acc[i][9]);
                acc[i][10] = fmaf(av, w2.z, acc[i][10]);
                acc[i][11] = fmaf(av, w2.w, acc[i][11]);
                acc[i][12] = fmaf(av, w3.x, acc[i][12]);
                acc[i][13] = fmaf(av, w3.y, acc[i][13]);
                acc[i][14] = fmaf(av, w3.z, acc[i][14]);
                acc[i][15] = fmaf(av, w3.w, acc[i][15]);
            }
        }
    }
    // gelu + store m1
    {
        const float4* b1q = reinterpret_cast<const float4*>(b1v);
        float4 bb0 = b1q[c * 4 + 0], bb1 = b1q[c * 4 + 1];
        float4 bb2 = b1q[c * 4 + 2], bb3 = b1q[c * 4 + 3];
        float bias[16] = {bb0.x, bb0.y, bb0.z, bb0.w, bb1.x, bb1.y, bb1.z, bb1.w,
                          bb2.x, bb2.y, bb2.z, bb2.w, bb3.x, bb3.y, bb3.z, bb3.w};
#pragma unroll
        for (int i = 0; i < 4; i++) {
            float* mrow = &M1[(r * 4 + i) * 512 + c * 16];
#pragma unroll
            for (int j = 0; j < 16; j++)
                mrow[j] = geluf_(acc[i][j] + bias[j]);
        }
    }
    __syncthreads();

    // GEMM2: 64x128, k=512; tile 4 tok x 4 ch per thread
    float a2[4][4];
#pragma unroll
    for (int i = 0; i < 4; i++)
#pragma unroll
        for (int j = 0; j < 4; j++) a2[i][j] = 0.f;
    {
        const float4* W24 = reinterpret_cast<const float4*>(W2); // [k][32 f4]
        for (int k = 0; k < 512; k++) {
            float4 w = W24[k * 32 + c];
#pragma unroll
            for (int i = 0; i < 4; i++) {
                float av = M1[(r * 4 + i) * 512 + k];
                a2[i][0] = fmaf(av, w.x, a2[i][0]);
                a2[i][1] = fmaf(av, w.y, a2[i][1]);
                a2[i][2] = fmaf(av, w.z, a2[i][2]);
                a2[i][3] = fmaf(av, w.w, a2[i][3]);
            }
        }
    }
    float4 bb = reinterpret_cast<const float4*>(b2v)[c];
#pragma unroll
    for (int i = 0; i < 4; i++) {
        int t = to + r * 4 + i;
        float4* op = reinterpret_cast<float4*>(out + t * 128 + c * 4);
        float4 xv = *op;
        float4 o;
        o.x = fmaf(g2, a2[i][0] + bb.x, xv.x);
        o.y = fmaf(g2, a2[i][1] + bb.y, xv.y);
        o.z = fmaf(g2, a2[i][2] + bb.z, xv.z);
        o.w = fmaf(g2, a2[i][3] + bb.w, xv.w);
        *op = o;
    }
}

// ---------------- launch ----------------------------------------------------
extern "C" void kernel_launch(void* const* d_in, const int* in_sizes, int n_in,
                              void* d_out, int out_size)
{
    const float* x        = (const float*)d_in[0];
    const float* c        = (const float*)d_in[1];
    const float* cln1_sw  = (const float*)d_in[2];
    const float* cln1_sb  = (const float*)d_in[3];
    const float* cln1_bw  = (const float*)d_in[4];
    const float* cln1_bb  = (const float*)d_in[5];
    const float* gate1_w  = (const float*)d_in[6];
    const float* gate1_b  = (const float*)d_in[7];
    const float* rnn_in_w = (const float*)d_in[8];
    const float* rnn_in_b = (const float*)d_in[9];
    const float* pos_emb  = (const float*)d_in[10];
    const float* rnn_wi   = (const float*)d_in[11];
    const float* rnn_bi   = (const float*)d_in[12];
    const float* rnn_wr   = (const float*)d_in[13];
    const float* rnn_br   = (const float*)d_in[14];
    const float* rnn_a    = (const float*)d_in[15];
    const float* rnn_out_w= (const float*)d_in[16];
    const float* rnn_out_b= (const float*)d_in[17];
    const float* cln2_sw  = (const float*)d_in[18];
    const float* cln2_sb  = (const float*)d_in[19];
    const float* cln2_bw  = (const float*)d_in[20];
    const float* cln2_bb  = (const float*)d_in[21];
    const float* gate2_w  = (const float*)d_in[22];
    const float* gate2_b  = (const float*)d_in[23];
    const float* mlp_w1   = (const float*)d_in[24];
    const float* mlp_b1   = (const float*)d_in[25];
    const float* mlp_w2   = (const float*)d_in[26];
    const float* mlp_b2   = (const float*)d_in[27];
    float* out = (float*)d_out;

    cudaFuncSetAttribute(k3_scan_out, cudaFuncAttributeMaxDynamicSharedMemorySize, 131072);
    cudaFuncSetAttribute(k4_mlp,      cudaFuncAttributeMaxDynamicSharedMemorySize, 163840);

    k0_scalars<<<8, 128>>>(c,
        cln1_sw, cln1_sb, cln1_bw, cln1_bb, gate1_w, gate1_b,
        cln2_sw, cln2_sb, cln2_bw, cln2_bb, gate2_w, gate2_b);
    k1_pre<<<1024, 256>>>(x, rnn_in_w, rnn_in_b, pos_emb,
                          rnn_wi, rnn_bi, rnn_wr, rnn_br, rnn_a);
    k2a_chunk<<<512, 256>>>();
    k2b_prefix<<<16, 128>>>();
    k3_scan_out<<<512, 256, 131072>>>(x, rnn_out_w, rnn_out_b, out);
    k4_mlp<<<1024, 512, 163840>>>(out, mlp_w1, mlp_b1, mlp_w2, mlp_b2);
}